// round 17
// baseline (speedup 1.0000x reference)
#include <cuda_runtime.h>
#include <cuda_fp16.h>
#include <cstdint>

#define NN   50000
#define EE   400000
#define NH   12
#define HC   32
#define D0   128
#define NHC  (NH*HC)   // 384
#define NC   2

// ---------------- scratch (static device globals) -----------------------------
__device__ __half g_xlh[(size_t)NN * NHC];     // 38.4 MB fp16 xl (edge-phase payload)
__device__ float g_xr[(size_t)NN * NHC];       // 76.8 MB
__device__ float g_act[(size_t)NN * HC];
__device__ float g_xlo[NN * NC];
__device__ float g_xro[NN * NC];
__device__ int   g_rowptr[NN + 1];
__device__ int   g_cnt[NN];                    // zero-init; count/scatter keep net-zero
__device__ int   g_adj[EE];                    // src node ids grouped by dst
__device__ int   g_btot[64];
__device__ int   g_boff[64];

// fp16 GEMM operands
__device__ __half g_ah[(size_t)NN * D0];       // A fp16 (single)
__device__ __half g_wh[2 * NHC * D0];          // W^T hi fp16, [z][n][k]
__device__ __half g_wl[2 * NHC * D0];          // W^T lo fp16

__device__ __forceinline__ float lrelu(float v) { return v > 0.f ? v : 0.2f * v; }

__device__ __forceinline__ uint32_t smem_u32(const void* p) {
    uint32_t a;
    asm("{ .reg .u64 t; cvta.to.shared.u64 t, %1; cvt.u32.u64 %0, t; }" : "=r"(a) : "l"(p));
    return a;
}
__device__ __forceinline__ void ldsm4(uint32_t* r, uint32_t addr) {
    asm volatile("ldmatrix.sync.aligned.m8n8.x4.shared.b16 {%0,%1,%2,%3}, [%4];"
                 : "=r"(r[0]), "=r"(r[1]), "=r"(r[2]), "=r"(r[3]) : "r"(addr));
}
__device__ __forceinline__ void mma_fp16(float* c, const uint32_t* a, uint32_t b0, uint32_t b1) {
    asm volatile(
        "mma.sync.aligned.m16n8k16.row.col.f32.f16.f16.f32 "
        "{%0,%1,%2,%3}, {%4,%5,%6,%7}, {%8,%9}, {%0,%1,%2,%3};"
        : "+f"(c[0]), "+f"(c[1]), "+f"(c[2]), "+f"(c[3])
        : "r"(a[0]), "r"(a[1]), "r"(a[2]), "r"(a[3]), "r"(b0), "r"(b1));
}
__device__ __forceinline__ void cp16(uint32_t s, const void* g) {
    asm volatile("cp.async.ca.shared.global [%0], [%1], 16;" :: "r"(s), "l"(g) : "memory");
}
__device__ __forceinline__ float4 ldh4(const __half* p) {
    uint2 raw = *reinterpret_cast<const uint2*>(p);
    __half2 h0 = *reinterpret_cast<__half2*>(&raw.x);
    __half2 h1 = *reinterpret_cast<__half2*>(&raw.y);
    float2 f0 = __half22float2(h0);
    float2 f1 = __half22float2(h1);
    return make_float4(f0.x, f0.y, f1.x, f1.y);
}

// ---------------- convert kernels -----------------------------------------------
template <int K>
__global__ void k_cvtA(const float* __restrict__ A, int M) {
    int i = blockIdx.x * blockDim.x + threadIdx.x;
    if (i >= M * K / 4) return;
    float4 v = reinterpret_cast<const float4*>(A)[i];
    __half2 h01 = __floats2half2_rn(v.x, v.y);
    __half2 h23 = __floats2half2_rn(v.z, v.w);
    uint2 h = make_uint2(*reinterpret_cast<uint32_t*>(&h01), *reinterpret_cast<uint32_t*>(&h23));
    reinterpret_cast<uint2*>(g_ah)[i] = h;
}

template <int K>
__global__ void k_cvtW(const float* __restrict__ Wa, const float* __restrict__ Wb) {
    int i = blockIdx.x * blockDim.x + threadIdx.x;
    if (i >= 2 * NHC * K) return;
    int z = i / (NHC * K);
    int r = i % (NHC * K);
    int n = r / K, k = r % K;
    const float* W = z ? Wb : Wa;
    float v = W[(size_t)k * NHC + n];
    __half h = __float2half_rn(v);
    __half l = __float2half_rn(v - __half2float(h));
    g_wh[(size_t)z * NHC * K + (size_t)n * K + k] = h;
    g_wl[(size_t)z * NHC * K + (size_t)n * K + k] = l;
}

// ---------------- fp16x2 HMMA GEMM with cp.async double-buffered k-loop --------
template <int K>
__global__ __launch_bounds__(256, 3)
void k_gemm_mma(const float* __restrict__ ba, const float* __restrict__ bb_,
                float* __restrict__ Cr, int M, int Ncol) {
    constexpr int BM = 128, BN = 64, BK = 32;
    constexpr int NK  = K / BK;
    constexpr int NST = (NK > 1) ? 2 : 1;
    constexpr int ST  = BK * 2 + 16;
    constexpr int SZA = BM * ST;
    constexpr int SZB = BN * ST;
    constexpr int STAGE = SZA + 2 * SZB;

    extern __shared__ char smem[];
    const uint32_t sb = smem_u32(smem);

    const float* bias = blockIdx.z ? bb_ : ba;
    const __half* wh = g_wh + (size_t)blockIdx.z * NHC * K;
    const __half* wl = g_wl + (size_t)blockIdx.z * NHC * K;

    const int rowBase = blockIdx.y * BM;
    const int colBase = blockIdx.x * BN;
    const int tid  = threadIdx.x;
    const int wid  = tid >> 5;
    const int lane = tid & 31;
    const int wm   = wid & 3;
    const int wn   = wid >> 2;

    auto load_stage = [&](int st, int ks) {
        uint32_t base = sb + st * STAGE;
#pragma unroll
        for (int i = tid; i < 512; i += 256) {
            int r = i >> 2, c = i & 3;
            int gr = rowBase + r;
            uint32_t da = base + r * ST + c * 16;
            if (gr < M) {
                cp16(da, g_ah + (size_t)gr * K + ks * BK + c * 8);
            } else {
                *reinterpret_cast<uint4*>(smem + st * STAGE + r * ST + c * 16) =
                    make_uint4(0, 0, 0, 0);
            }
        }
        {
            int n = tid >> 2, c = tid & 3;
            const size_t off = (size_t)(colBase + n) * K + ks * BK + c * 8;
            cp16(base + SZA + n * ST + c * 16,       wh + off);
            cp16(base + SZA + SZB + n * ST + c * 16, wl + off);
        }
    };

    const int g  = lane >> 3;
    const int ri = lane & 7;

    float acc[2][4][4];
#pragma unroll
    for (int mt = 0; mt < 2; mt++)
#pragma unroll
        for (int nt = 0; nt < 4; nt++)
#pragma unroll
            for (int q = 0; q < 4; q++) acc[mt][nt][q] = 0.f;

    load_stage(0, 0);
    asm volatile("cp.async.commit_group;" ::: "memory");

#pragma unroll
    for (int ks = 0; ks < NK; ks++) {
        if (ks + 1 < NK) {
            load_stage((ks + 1) % NST, ks + 1);
            asm volatile("cp.async.commit_group;" ::: "memory");
            asm volatile("cp.async.wait_group 1;" ::: "memory");
        } else {
            asm volatile("cp.async.wait_group 0;" ::: "memory");
        }
        __syncthreads();

        const uint32_t base = sb + (ks % NST) * STAGE;
#pragma unroll
        for (int kk = 0; kk < 2; kk++) {
            uint32_t aH[2][4], bH[2][4], bL[2][4];
#pragma unroll
            for (int mt = 0; mt < 2; mt++) {
                int row = wm * 32 + mt * 16 + ri + (g & 1) * 8;
                int col = kk * 16 + (g >> 1) * 8;
                ldsm4(aH[mt], base + row * ST + col * 2);
            }
#pragma unroll
            for (int p = 0; p < 2; p++) {
                int row = wn * 32 + p * 16 + ri + (g >> 1) * 8;
                int col = kk * 16 + (g & 1) * 8;
                uint32_t bd = base + SZA + row * ST + col * 2;
                ldsm4(bH[p], bd);
                ldsm4(bL[p], bd + SZB);
            }
#pragma unroll
            for (int mt = 0; mt < 2; mt++)
#pragma unroll
                for (int nt = 0; nt < 4; nt++) {
                    int p = nt >> 1, o = (nt & 1) * 2;
                    mma_fp16(acc[mt][nt], aH[mt], bH[p][o], bH[p][o + 1]);
                    mma_fp16(acc[mt][nt], aH[mt], bL[p][o], bL[p][o + 1]);
                }
        }
        __syncthreads();
    }

    const bool toH = (blockIdx.z == 0);
#pragma unroll
    for (int mt = 0; mt < 2; mt++) {
#pragma unroll
        for (int nt = 0; nt < 4; nt++) {
            int gr = rowBase + wm * 32 + mt * 16 + (lane >> 2);
            int gc = colBase + wn * 32 + nt * 8 + (lane & 3) * 2;
            float b0 = bias[gc], b1 = bias[gc + 1];
            if (gr < M) {
                float v0 = acc[mt][nt][0] + b0, v1 = acc[mt][nt][1] + b1;
                if (toH) {
                    __half2 hh = __floats2half2_rn(v0, v1);
                    *reinterpret_cast<__half2*>(&g_xlh[(size_t)gr * Ncol + gc]) = hh;
                } else {
                    *reinterpret_cast<float2*>(&Cr[(size_t)gr * Ncol + gc]) = make_float2(v0, v1);
                }
            }
            if (gr + 8 < M) {
                float v0 = acc[mt][nt][2] + b0, v1 = acc[mt][nt][3] + b1;
                if (toH) {
                    __half2 hh = __floats2half2_rn(v0, v1);
                    *reinterpret_cast<__half2*>(&g_xlh[(size_t)(gr + 8) * Ncol + gc]) = hh;
                } else {
                    *reinterpret_cast<float2*>(&Cr[(size_t)(gr + 8) * Ncol + gc]) = make_float2(v0, v1);
                }
            }
        }
    }
}

// ---------------- CSR build ----------------------------------------------------
__global__ void k_count(const int* __restrict__ dst, int* cnt) {
    int i = blockIdx.x * blockDim.x + threadIdx.x;
    if (i < EE) atomicAdd(&cnt[dst[i]], 1);
}

// Multi-block scan: A) 49 blocks do local inclusive scans (+ block totals),
// B) one small block scans the 49 totals, C) 49 blocks add block offsets.
__global__ void k_scanA(const int* __restrict__ cnt, int* __restrict__ rowptr) {
    __shared__ int wsum[32];
    const int tid  = threadIdx.x;
    const int lane = tid & 31, wid = tid >> 5;
    const int i = blockIdx.x * 1024 + tid;
    int v = (i < NN) ? cnt[i] : 0;

    int x = v;
#pragma unroll
    for (int o = 1; o < 32; o <<= 1) {
        int t = __shfl_up_sync(0xffffffffu, x, o);
        if (lane >= o) x += t;
    }
    if (lane == 31) wsum[wid] = x;
    __syncthreads();
    if (wid == 0) {
        int s = wsum[lane];
#pragma unroll
        for (int o = 1; o < 32; o <<= 1) {
            int t = __shfl_up_sync(0xffffffffu, s, o);
            if (lane >= o) s += t;
        }
        wsum[lane] = s;
    }
    __syncthreads();
    int incl = x + (wid ? wsum[wid - 1] : 0);
    if (i < NN) rowptr[i + 1] = incl;
    if (tid == 1023) g_btot[blockIdx.x] = incl;
}

__global__ void k_scanB(int nblk) {
    // single warp-pair scan over nblk (<=64) totals
    __shared__ int s_t[64];
    int t = threadIdx.x;
    s_t[t] = (t < nblk) ? g_btot[t] : 0;
    __syncthreads();
    if (t == 0) {
        int run = 0;
        for (int b = 0; b < nblk; b++) { int tv = s_t[b]; s_t[b] = run; run += tv; }
    }
    __syncthreads();
    if (t < nblk) g_boff[t] = s_t[t];   // exclusive offsets
}

__global__ void k_scanC(int* __restrict__ rowptr) {
    const int i = blockIdx.x * 1024 + threadIdx.x;
    int off = g_boff[blockIdx.x];
    if (i < NN) rowptr[i + 1] += off;
    if (i == 0) rowptr[0] = 0;
}

__global__ void k_scatter(const int* __restrict__ dst, const int* __restrict__ src,
                          const int* __restrict__ rowptr, int* cnt, int* adj) {
    int i = blockIdx.x * blockDim.x + threadIdx.x;
    if (i < EE) {
        int d = dst[i];
        int pos = rowptr[d] + (atomicAdd(&cnt[d], -1) - 1);
        adj[pos] = src[i];
    }
}

// ---------------- fused GATv2 layer: warp per (node, head-group) ---------------
// Self-anchored softmax (no fmax/rescale chain) + x2 edge unroll with
// independent accumulators. xl gathered as fp16; fp32 math throughout.
__device__ __forceinline__ float head_logit(float4 xv, float4 xr, float4 a) {
    float t = lrelu(xv.x + xr.x) * a.x
            + lrelu(xv.y + xr.y) * a.y
            + lrelu(xv.z + xr.z) * a.z
            + lrelu(xv.w + xr.w) * a.w;
    t += __shfl_xor_sync(0xffffffffu, t, 1);
    t += __shfl_xor_sync(0xffffffffu, t, 2);
    t += __shfl_xor_sync(0xffffffffu, t, 4);
    return t;
}

__global__ __launch_bounds__(192)
void k_aggregate(const float* __restrict__ att, const float* __restrict__ bias) {
    __shared__ float4 s_part[2][3][32];
    const int w    = threadIdx.x >> 5;
    const int lane = threadIdx.x & 31;
    const int nl   = w / 3;
    const int g    = w % 3;
    const int node = blockIdx.x * 2 + nl;

    const float4* a4  = reinterpret_cast<const float4*>(att);
    const float4 attv = a4[g * 32 + lane];
    const float4 xrv  = reinterpret_cast<const float4*>(g_xr + (size_t)node * NHC)[g * 32 + lane];
    const float4 xv0  = ldh4(g_xlh + (size_t)node * NHC + g * 128 + lane * 4);

    // anchor m = self logit; self contributes e=1
    const float m = head_logit(xv0, xrv, attv);
    float d0 = 1.f, d1 = 0.f;
    float4 acc0 = xv0;
    float4 acc1 = make_float4(0.f, 0.f, 0.f, 0.f);

    const int start = g_rowptr[node], end = g_rowptr[node + 1];
    int p = start;
    for (; p + 1 < end; p += 2) {
        int sa = g_adj[p];
        int sb = g_adj[p + 1];
        float4 xva = ldh4(g_xlh + (size_t)sa * NHC + g * 128 + lane * 4);
        float4 xvb = ldh4(g_xlh + (size_t)sb * NHC + g * 128 + lane * 4);
        float ta = head_logit(xva, xrv, attv);
        float tb = head_logit(xvb, xrv, attv);
        float ea = __expf(ta - m);
        float eb = __expf(tb - m);
        d0 += ea;  d1 += eb;
        acc0.x += ea * xva.x;  acc1.x += eb * xvb.x;
        acc0.y += ea * xva.y;  acc1.y += eb * xvb.y;
        acc0.z += ea * xva.z;  acc1.z += eb * xvb.z;
        acc0.w += ea * xva.w;  acc1.w += eb * xvb.w;
    }
    if (p < end) {
        int sa = g_adj[p];
        float4 xva = ldh4(g_xlh + (size_t)sa * NHC + g * 128 + lane * 4);
        float ta = head_logit(xva, xrv, attv);
        float ea = __expf(ta - m);
        d0 += ea;
        acc0.x += ea * xva.x;
        acc0.y += ea * xva.y;
        acc0.z += ea * xva.z;
        acc0.w += ea * xva.w;
    }

    float dinv = 1.f / (d0 + d1);
    s_part[nl][g][lane] = make_float4((acc0.x + acc1.x) * dinv, (acc0.y + acc1.y) * dinv,
                                      (acc0.z + acc1.z) * dinv, (acc0.w + acc1.w) * dinv);
    __syncthreads();

    if (g == 0) {
        float4 p0 = s_part[nl][0][lane];
        float4 p1 = s_part[nl][1][lane];
        float4 p2 = s_part[nl][2][lane];
        float4 s4 = make_float4(p0.x + p1.x + p2.x, p0.y + p1.y + p2.y,
                                p0.z + p1.z + p2.z, p0.w + p1.w + p2.w);
#pragma unroll
        for (int o = 8; o <= 16; o <<= 1) {
            s4.x += __shfl_xor_sync(0xffffffffu, s4.x, o);
            s4.y += __shfl_xor_sync(0xffffffffu, s4.y, o);
            s4.z += __shfl_xor_sync(0xffffffffu, s4.z, o);
            s4.w += __shfl_xor_sync(0xffffffffu, s4.w, o);
        }
        if (lane < 8) {
            float4 b = reinterpret_cast<const float4*>(bias)[lane];
            float4 o4;
            o4.x = s4.x * (1.f / NH) + b.x;
            o4.y = s4.y * (1.f / NH) + b.y;
            o4.z = s4.z * (1.f / NH) + b.z;
            o4.w = s4.w * (1.f / NH) + b.w;
            o4.x = o4.x > 0.f ? o4.x : (__expf(o4.x) - 1.f);
            o4.y = o4.y > 0.f ? o4.y : (__expf(o4.y) - 1.f);
            o4.z = o4.z > 0.f ? o4.z : (__expf(o4.z) - 1.f);
            o4.w = o4.w > 0.f ? o4.w : (__expf(o4.w) - 1.f);
            reinterpret_cast<float4*>(g_act + (size_t)node * HC)[lane] = o4;
            __half2 p01 = __floats2half2_rn(o4.x, o4.y);
            __half2 p23 = __floats2half2_rn(o4.z, o4.w);
            uint2 u = make_uint2(*reinterpret_cast<uint32_t*>(&p01),
                                 *reinterpret_cast<uint32_t*>(&p23));
            *reinterpret_cast<uint2*>(g_ah + (size_t)node * HC + lane * 4) = u;
        }
    }
}

// ---------------- output GATv2 layer (heads=1, C=2) ----------------------------
__global__ void k_lin_out(const float* __restrict__ Wl, const float* __restrict__ bl,
                          const float* __restrict__ Wr, const float* __restrict__ br) {
    int node = (blockIdx.x * blockDim.x + threadIdx.x) >> 5;
    int lane = threadIdx.x & 31;
    if (node >= NN) return;
    float hv = g_act[(size_t)node * HC + lane];
#pragma unroll
    for (int j = 0; j < NC; j++) {
        float a = hv * Wl[lane * NC + j];
        float b = hv * Wr[lane * NC + j];
#pragma unroll
        for (int o = 16; o; o >>= 1) {
            a += __shfl_xor_sync(0xffffffffu, a, o);
            b += __shfl_xor_sync(0xffffffffu, b, o);
        }
        if (lane == 0) {
            g_xlo[node * NC + j] = a + bl[j];
            g_xro[node * NC + j] = b + br[j];
        }
    }
}

__global__ void k_out(const float* __restrict__ atto, const float* __restrict__ biaso,
                      float* __restrict__ out) {
    int node = (blockIdx.x * blockDim.x + threadIdx.x) >> 5;
    int lane = threadIdx.x & 31;
    if (node >= NN) return;
    float x0 = g_xlo[2 * node], x1 = g_xlo[2 * node + 1];
    float r0 = g_xro[2 * node], r1 = g_xro[2 * node + 1];
    float a0 = atto[0], a1 = atto[1];
    float sl = a0 * lrelu(x0 + r0) + a1 * lrelu(x1 + r1);

    // self-anchored accumulation (lane-strided)
    float d = (lane == 0) ? 1.f : 0.f;
    float s0 = (lane == 0) ? x0 : 0.f;
    float s1 = (lane == 0) ? x1 : 0.f;

    const int start = g_rowptr[node], end = g_rowptr[node + 1];
    for (int p = start + lane; p < end; p += 32) {
        int s = g_adj[p];
        float y0 = g_xlo[2 * s], y1 = g_xlo[2 * s + 1];
        float l  = a0 * lrelu(y0 + r0) + a1 * lrelu(y1 + r1);
        float w  = __expf(l - sl);
        d  += w;
        s0 += w * y0;
        s1 += w * y1;
    }
#pragma unroll
    for (int o = 16; o; o >>= 1) {
        d  += __shfl_xor_sync(0xffffffffu, d, o);
        s0 += __shfl_xor_sync(0xffffffffu, s0, o);
        s1 += __shfl_xor_sync(0xffffffffu, s1, o);
    }
    if (lane == 0) {
        float dinv = 1.f / d;
        out[2 * node]     = s0 * dinv + biaso[0];
        out[2 * node + 1] = s1 * dinv + biaso[1];
    }
}

// ---------------- launch --------------------------------------------------------
extern "C" void kernel_launch(void* const* d_in, const int* in_sizes, int n_in,
                              void* d_out, int out_size) {
    const float* x     = (const float*)d_in[0];
    const int*   ei    = (const int*)d_in[1];
    const float* Wl0   = (const float*)d_in[2];
    const float* bl0   = (const float*)d_in[3];
    const float* Wr0   = (const float*)d_in[4];
    const float* br0   = (const float*)d_in[5];
    const float* att0  = (const float*)d_in[6];
    const float* bias0 = (const float*)d_in[7];
    const float* Wl1   = (const float*)d_in[8];
    const float* bl1   = (const float*)d_in[9];
    const float* Wr1   = (const float*)d_in[10];
    const float* br1   = (const float*)d_in[11];
    const float* att1  = (const float*)d_in[12];
    const float* bias1 = (const float*)d_in[13];
    const float* Wlo   = (const float*)d_in[14];
    const float* blo   = (const float*)d_in[15];
    const float* Wro   = (const float*)d_in[16];
    const float* bro   = (const float*)d_in[17];
    const float* atto  = (const float*)d_in[18];
    const float* biaso = (const float*)d_in[19];
    float* out = (float*)d_out;

    const int* src = ei;        // edge_index[0]
    const int* dst = ei + EE;   // edge_index[1]

    float *pxr;
    int *pcnt, *prow, *padj;
    cudaGetSymbolAddress((void**)&pxr,  g_xr);
    cudaGetSymbolAddress((void**)&pcnt, g_cnt);
    cudaGetSymbolAddress((void**)&prow, g_rowptr);
    cudaGetSymbolAddress((void**)&padj, g_adj);

    const int smem128 = 2 * 20480;
    const int smem32  = 1 * 20480;
    cudaFuncSetAttribute(k_gemm_mma<128>, cudaFuncAttributeMaxDynamicSharedMemorySize, smem128);
    cudaFuncSetAttribute(k_gemm_mma<32>,  cudaFuncAttributeMaxDynamicSharedMemorySize, smem32);

    dim3 gg(NHC / 64, (NN + 127) / 128, 2);
    const int NBLK = (NN + 1023) / 1024;   // 49

    // layer 0
    k_cvtA<128><<<(NN * D0 / 4 + 255) / 256, 256>>>(x, NN);
    k_cvtW<128><<<(2 * NHC * 128 + 255) / 256, 256>>>(Wl0, Wr0);
    k_count<<<(EE + 255) / 256, 256>>>(dst, pcnt);
    k_scanA<<<NBLK, 1024>>>(pcnt, prow);
    k_scanB<<<1, 64>>>(NBLK);
    k_scanC<<<NBLK, 1024>>>(prow);
    k_gemm_mma<128><<<gg, 256, smem128>>>(bl0, br0, pxr, NN, NHC);
    k_scatter<<<(EE + 255) / 256, 256>>>(dst, src, prow, pcnt, padj);
    k_aggregate<<<NN / 2, 192>>>(att0, bias0);   // writes g_ah too

    // layer 1 (A fp16 comes from aggregate epilogue)
    k_cvtW<32><<<(2 * NHC * 32 + 255) / 256, 256>>>(Wl1, Wr1);
    k_gemm_mma<32><<<gg, 256, smem32>>>(bl1, br1, pxr, NN, NHC);
    k_aggregate<<<NN / 2, 192>>>(att1, bias1);

    // output layer
    k_lin_out<<<(NN + 7) / 8, 256>>>(Wlo, blo, Wro, bro);
    k_out    <<<(NN + 7) / 8, 256>>>(atto, biaso, out);
}